// round 6
// baseline (speedup 1.0000x reference)
#include <cuda_runtime.h>

#define BS      64
#define NKP     17
#define A       8400
#define GRIDSZ  80             // 640 / stride(8)
#define CH      (3*NKP)        // 51
#define ROWLEN  A
#define BATCHSZ (CH*A)         // 428400 floats / batch
#define NROWS   (BS*NKP)       // 1088 conf rows
#define V8ROW   (A/8)          // 1050 float8 / row
#define TPB     256
#define NFULL   4              // 4*256 = 1024 full float8 chunks
#define NTAIL   (V8ROW - NFULL*TPB)   // 26
#define NTOTAL  9139200.0f     // 64*17*8400
#define LN2F    0.69314718056f
#define L2CLAMP (-144.26950409f)   // -100 / ln2

__device__ float        g_acc[3];   // [0] dense sum log2(1-c), [1] vis corr (log2), [2] xy sqerr
__device__ unsigned int g_cnt;      // completed-block counter (zero-init, self-resetting)

struct F8 { float v[8]; };

// volatile: pins issue order -> all loads batched before compute, results stay live
__device__ __forceinline__ void ld256v(F8& r, const float* a) {
    asm volatile("ld.global.nc.L2::evict_last.v8.b32 {%0,%1,%2,%3,%4,%5,%6,%7}, [%8];"
        : "=f"(r.v[0]), "=f"(r.v[1]), "=f"(r.v[2]), "=f"(r.v[3]),
          "=f"(r.v[4]), "=f"(r.v[5]), "=f"(r.v[6]), "=f"(r.v[7])
        : "l"(a));
}

__global__ __launch_bounds__(TPB, 4) void k_fused(
    const float* __restrict__ out,
    const float* __restrict__ gtk,
    const int*   __restrict__ vis,
    float*       __restrict__ res)
{
    const int row = blockIdx.x;                 // 0..1087 == (b,k) flat
    const int b   = row / NKP;
    const int k   = row - b * NKP;
    const float* __restrict__ p = out + b * BATCHSZ + (3*k + 2) * ROWLEN + threadIdx.x * 8;
    const int tid = threadIdx.x;

    // ---- PHASE 1: issue ALL 5 loads back-to-back (forced MLP=5) ----
    F8 c[5];
    ld256v(c[0], p);
    ld256v(c[1], p + 1*TPB*8);
    ld256v(c[2], p + 2*TPB*8);
    ld256v(c[3], p + 3*TPB*8);
    if (tid < NTAIL) {
        ld256v(c[4], p + 4*TPB*8);
    } else {
        #pragma unroll
        for (int j = 0; j < 8; j++) c[4].v[j] = 0.f;   // log2(1-0)=0 contributes nothing
    }

    // ---- PHASE 2: sum max(log2(1-c), -100/ln2), 4 independent accumulators ----
    float s0 = 0.f, s1 = 0.f, s2 = 0.f, s3 = 0.f;
    #pragma unroll
    for (int i = 0; i < 5; i++) {
        s0 += fmaxf(__log2f(1.0f - c[i].v[0]), L2CLAMP);
        s1 += fmaxf(__log2f(1.0f - c[i].v[1]), L2CLAMP);
        s2 += fmaxf(__log2f(1.0f - c[i].v[2]), L2CLAMP);
        s3 += fmaxf(__log2f(1.0f - c[i].v[3]), L2CLAMP);
        s0 += fmaxf(__log2f(1.0f - c[i].v[4]), L2CLAMP);
        s1 += fmaxf(__log2f(1.0f - c[i].v[5]), L2CLAMP);
        s2 += fmaxf(__log2f(1.0f - c[i].v[6]), L2CLAMP);
        s3 += fmaxf(__log2f(1.0f - c[i].v[7]), L2CLAMP);
    }
    float s = (s0 + s1) + (s2 + s3);

    // ---- sparse: this block's (b,k) gather, one lane ----
    if (tid == TPB - 1) {
        const float gx = gtk[2*row], gy = gtk[2*row + 1];
        if (vis[row] == 1) {
            const int idx = (int)(gy * 0.125f) * GRIDSZ + (int)(gx * 0.125f);
            const float* rb = out + b * BATCHSZ + 3 * k * ROWLEN;
            const float xg = rb[idx];
            const float yg = rb[ROWLEN + idx];
            const float cg = rb[2*ROWLEN + idx];
            const float dx = xg - gx, dy = yg - gy;
            atomicAdd(&g_acc[2], dx*dx + dy*dy);
            atomicAdd(&g_acc[1], fmaxf(__log2f(cg), L2CLAMP)
                               - fmaxf(__log2f(1.0f - cg), L2CLAMP));
        }
    }

    // ---- block reduction ----
    #pragma unroll
    for (int o = 16; o > 0; o >>= 1)
        s += __shfl_down_sync(0xffffffffu, s, o);

    __shared__ float sh[TPB/32];
    if ((tid & 31) == 0) sh[tid >> 5] = s;
    __syncthreads();

    if (tid == 0) {
        float v2 = 0.f;
        #pragma unroll
        for (int w = 0; w < TPB/32; w++) v2 += sh[w];
        atomicAdd(&g_acc[0], v2);

        // ---- last-block finalize + self-reset (graph-replay deterministic) ----
        __threadfence();
        const unsigned int ticket = atomicAdd(&g_cnt, 1u);
        if (ticket == (unsigned)(gridDim.x - 1)) {
            __threadfence();
            const float a0 = *(volatile float*)&g_acc[0];
            const float a1 = *(volatile float*)&g_acc[1];
            const float a2 = *(volatile float*)&g_acc[2];
            res[0] = -(a0 + a1) * (LN2F / NTOTAL) + a2 * (1.0f / (float)BS);
            *(volatile float*)&g_acc[0] = 0.f;
            *(volatile float*)&g_acc[1] = 0.f;
            *(volatile float*)&g_acc[2] = 0.f;
            *(volatile unsigned int*)&g_cnt = 0u;
        }
    }
}

extern "C" void kernel_launch(void* const* d_in, const int* in_sizes, int n_in,
                              void* d_out, int out_size) {
    const float* out_t = (const float*)d_in[0];   // (64, 51, 8400) f32
    const float* gtk   = (const float*)d_in[2];   // (64, 17, 2) f32
    const int*   vis   = (const int*)  d_in[3];   // (64, 17) i32
    float* res = (float*)d_out;

    k_fused<<<NROWS, TPB>>>(out_t, gtk, vis, res);
}

// round 7
// speedup vs baseline: 1.0201x; 1.0201x over previous
#include <cuda_runtime.h>

#define BS      64
#define NKP     17
#define A       8400
#define GRIDSZ  80
#define CH      (3*NKP)        // 51
#define ROWLEN  A
#define BATCHSZ (CH*A)         // 428400 floats / batch
#define NROWS   (BS*NKP)       // 1088
#define V8ROW   (A/8)          // 1050 float8 / row
#define NCHUNK  (NROWS*V8ROW)  // 1,142,400 float8 chunks total
#define NBLK    148
#define TPB     1024
#define NTHREADS (NBLK*TPB)    // 151,552
#define NITER   8              // ceil(NCHUNK/NTHREADS)
#define NTOTAL  9139200.0f
#define LN2F    0.69314718056f
#define L2CLAMP (-144.26950409f)   // -100 / ln2

__device__ float        g_acc[3];
__device__ unsigned int g_cnt;

struct F8 { float v[8]; };

__device__ __forceinline__ F8 ld256(const float* a) {
    F8 r;
    asm("ld.global.nc.L2::evict_last.v8.b32 {%0,%1,%2,%3,%4,%5,%6,%7}, [%8];"
        : "=f"(r.v[0]), "=f"(r.v[1]), "=f"(r.v[2]), "=f"(r.v[3]),
          "=f"(r.v[4]), "=f"(r.v[5]), "=f"(r.v[6]), "=f"(r.v[7])
        : "l"(a));
    return r;
}

__global__ __launch_bounds__(TPB, 1) void k_fused(
    const float* __restrict__ out,
    const float* __restrict__ gtk,
    const int*   __restrict__ vis,
    float*       __restrict__ res)
{
    const int tid = threadIdx.x;
    const int g   = blockIdx.x * TPB + tid;

    // ---- sparse: global threads < 1088 each own one (b,k) ----
    if (g < NROWS) {
        const float gx = gtk[2*g], gy = gtk[2*g + 1];
        if (vis[g] == 1) {
            const int gb = g / NKP;
            const int gk = g - gb * NKP;
            const int idx = (int)(gy * 0.125f) * GRIDSZ + (int)(gx * 0.125f);
            const float* rb = out + gb * BATCHSZ + 3 * gk * ROWLEN;
            const float xg = rb[idx];
            const float yg = rb[ROWLEN + idx];
            const float cg = rb[2*ROWLEN + idx];
            const float dx = xg - gx, dy = yg - gy;
            atomicAdd(&g_acc[2], dx*dx + dy*dy);
            atomicAdd(&g_acc[1], fmaxf(__log2f(cg), L2CLAMP)
                               - fmaxf(__log2f(1.0f - cg), L2CLAMP));
        }
    }

    // ---- dense: flat chunk-space, ~8 chunks/thread, coalesced ----
    float s0 = 0.f, s1 = 0.f;
    #pragma unroll
    for (int i = 0; i < NITER; i++) {
        const int idx = g + i * NTHREADS;
        if (idx < NCHUNK) {
            const int row = idx / V8ROW;            // (b,k) flat
            const int c   = idx - row * V8ROW;      // chunk within row
            const int b   = row / NKP;
            const int k   = row - b * NKP;
            const F8 v = ld256(out + b * BATCHSZ + (3*k + 2) * ROWLEN + c * 8);
            s0 += fmaxf(__log2f(1.0f - v.v[0]), L2CLAMP);
            s1 += fmaxf(__log2f(1.0f - v.v[1]), L2CLAMP);
            s0 += fmaxf(__log2f(1.0f - v.v[2]), L2CLAMP);
            s1 += fmaxf(__log2f(1.0f - v.v[3]), L2CLAMP);
            s0 += fmaxf(__log2f(1.0f - v.v[4]), L2CLAMP);
            s1 += fmaxf(__log2f(1.0f - v.v[5]), L2CLAMP);
            s0 += fmaxf(__log2f(1.0f - v.v[6]), L2CLAMP);
            s1 += fmaxf(__log2f(1.0f - v.v[7]), L2CLAMP);
        }
    }
    float s = s0 + s1;

    // ---- block reduction (1024 threads) ----
    #pragma unroll
    for (int o = 16; o > 0; o >>= 1)
        s += __shfl_down_sync(0xffffffffu, s, o);

    __shared__ float sh[TPB/32];
    if ((tid & 31) == 0) sh[tid >> 5] = s;
    __syncthreads();

    if (tid < 32) {
        float v = sh[tid];
        #pragma unroll
        for (int o = 16; o > 0; o >>= 1)
            v += __shfl_down_sync(0xffffffffu, v, o);

        if (tid == 0) {
            atomicAdd(&g_acc[0], v);     // ONE atomic per block (148 total)

            // ---- last-block finalize + self-reset ----
            __threadfence();
            const unsigned int ticket = atomicAdd(&g_cnt, 1u);
            if (ticket == (unsigned)(gridDim.x - 1)) {
                __threadfence();
                const float a0 = *(volatile float*)&g_acc[0];
                const float a1 = *(volatile float*)&g_acc[1];
                const float a2 = *(volatile float*)&g_acc[2];
                res[0] = -(a0 + a1) * (LN2F / NTOTAL) + a2 * (1.0f / (float)BS);
                *(volatile float*)&g_acc[0] = 0.f;
                *(volatile float*)&g_acc[1] = 0.f;
                *(volatile float*)&g_acc[2] = 0.f;
                *(volatile unsigned int*)&g_cnt = 0u;
            }
        }
    }
}

extern "C" void kernel_launch(void* const* d_in, const int* in_sizes, int n_in,
                              void* d_out, int out_size) {
    const float* out_t = (const float*)d_in[0];   // (64, 51, 8400) f32
    const float* gtk   = (const float*)d_in[2];   // (64, 17, 2) f32
    const int*   vis   = (const int*)  d_in[3];   // (64, 17) i32
    float* res = (float*)d_out;

    k_fused<<<NBLK, TPB>>>(out_t, gtk, vis, res);
}